// round 10
// baseline (speedup 1.0000x reference)
#include <cuda_runtime.h>
#include <math.h>

#define NB 4
#define CD 96
#define LL 96
#define PLANE 9216
#define NPIX 36864
#define BPL 36864
#define OC 192
#define HID 255
#define HP 512
#define KP 256
#define EPSF 1e-5f

__device__ float g_ln[NB*CD*PLANE];
__device__ float g_yt2[CD*BPL];
__device__ float g_qkv2[OC*BPL];
__device__ float g_ao2[OC*BPL];
__device__ float g_res[NB*CD*PLANE];
__device__ float g_h[(size_t)NB*HP*PLANE];
__device__ float g_gate[(size_t)NB*KP*PLANE];
__device__ float g_winpad[HP*CD];
__device__ float g_woutpad[CD*KP];
__device__ float g_scale[OC], g_shift[OC];
__device__ float g_oscale[OC], g_oshift[OC];
__device__ double g_part[384*8*6];
__device__ double g_stat[OC*2];
__device__ float g_sscale[24], g_sshift[24];
__device__ float g_se[12*96];
__device__ float g_Pq[21*96], g_Pk[21*96];

__device__ __constant__ int PA[21] = {0,0,0,0,0,0,1,1,1,1,1,2,2,2,2,3,3,3,4,4,5};
__device__ __constant__ int PB[21] = {0,1,2,3,4,5,1,2,3,4,5,2,3,4,5,3,4,5,4,5,5};

__global__ void k_zerostat(){
  int t = threadIdx.x;
  if (t < OC){ g_stat[t*2]=0.0; g_stat[t*2+1]=0.0; }
}

__global__ void k_prep(const float* __restrict__ win, const float* __restrict__ wout){
  int t = blockIdx.x*blockDim.x + threadIdx.x;
  if (t < HP*CD){
    int m = t/CD;
    g_winpad[t] = (m<510)? win[t] : 0.f;
  }
  if (t < CD*KP){
    int m = t/KP, k = t%KP;
    g_woutpad[t] = (k<HID)? wout[m*HID+k] : 0.f;
  }
  if (t < NB*PLANE){
    int n = t/PLANE, hw = t%PLANE;
    g_gate[((long)n*KP+HID)*PLANE + hw] = 0.f;
  }
}

__global__ void k_ln(const float* __restrict__ src, const float* __restrict__ w,
                     const float* __restrict__ b){
  int pix = blockIdx.x*blockDim.x + threadIdx.x;
  if (pix >= NPIX) return;
  int n = pix / PLANE, hw = pix % PLANE;
  const float* xp = src + (long)n*CD*PLANE + hw;
  float s=0.f, ss=0.f;
  #pragma unroll 8
  for (int c=0;c<CD;c++){ float v = xp[(long)c*PLANE]; s+=v; ss+=v*v; }
  float mn = s*(1.f/CD);
  float inv = rsqrtf(ss*(1.f/CD) - mn*mn + EPSF);
  float* op = g_ln + (long)n*CD*PLANE + hw;
  #pragma unroll 8
  for (int c=0;c<CD;c++){
    float v = xp[(long)c*PLANE];
    op[(long)c*PLANE] = (v-mn)*inv*w[c] + b[c];
  }
}

__global__ void k_transH(){
  __shared__ float t[32][33];
  int nc = blockIdx.z; int n = nc/CD, c = nc%CD;
  int h0 = blockIdx.y*32, w0 = blockIdx.x*32;
  const float* in = g_ln + (long)nc*PLANE;
  t[threadIdx.y][threadIdx.x] = in[(h0+threadIdx.y)*LL + w0+threadIdx.x];
  __syncthreads();
  g_yt2[(long)c*BPL + n*PLANE + (w0+threadIdx.y)*LL + (h0+threadIdx.x)] = t[threadIdx.x][threadIdx.y];
}

template<int BM,int TM,int KTOT,int STAT,bool RES>
__global__ void __launch_bounds__(256) k_gemm(const float* __restrict__ A,
                        const float* __restrict__ Bb,
                        float* __restrict__ Cb, const float* __restrict__ Rb,
                        int N, long sB, long sC){
  const int BN = 128, KT = KTOT/16, NA = BM/16;
  const float* B = Bb + (long)blockIdx.z * sB;
  float* C = Cb + (long)blockIdx.z * sC;
  __shared__ __align__(16) float As[2][16][BM+1];
  __shared__ __align__(16) float Bs[2][16][BN+4];
  int tid = threadIdx.x;
  int tx = tid % 16, ty = tid / 16;
  int m0 = blockIdx.y*BM, n0 = blockIdx.x*BN;
  float acc[TM][8];
  #pragma unroll
  for (int u=0;u<TM;u++)
    #pragma unroll
    for (int v=0;v<8;v++) acc[u][v]=0.f;
  {
    #pragma unroll
    for (int it=0; it<NA; it++){
      int e = tid + it*256;
      As[0][e&15][e>>4] = A[(long)(m0 + (e>>4))*KTOT + (e&15)];
    }
    #pragma unroll
    for (int it=0; it<2; it++){
      int e4 = tid + it*256;
      *reinterpret_cast<float4*>(&Bs[0][e4/32][(e4%32)*4]) =
        *reinterpret_cast<const float4*>(&B[(long)(e4/32)*N + n0 + (e4%32)*4]);
    }
  }
  __syncthreads();
  for (int kt=0; kt<KT; kt++){
    int cur = kt & 1, nxt = cur ^ 1;
    float ra[NA]; float4 rb[2];
    if (kt+1 < KT){
      int k0 = (kt+1)*16;
      #pragma unroll
      for (int it=0; it<NA; it++){
        int e = tid + it*256;
        ra[it] = A[(long)(m0 + (e>>4))*KTOT + k0 + (e&15)];
      }
      #pragma unroll
      for (int it=0; it<2; it++){
        int e4 = tid + it*256;
        rb[it] = *reinterpret_cast<const float4*>(&B[(long)(k0 + e4/32)*N + n0 + (e4%32)*4]);
      }
    }
    const float (*Ac)[BM+1] = As[cur];
    const float (*Bc)[BN+4] = Bs[cur];
    #pragma unroll
    for (int k=0;k<16;k++){
      float a[TM], b[8];
      #pragma unroll
      for (int u=0;u<TM;u++) a[u] = Ac[k][ty*TM+u];
      float4 b0 = *reinterpret_cast<const float4*>(&Bc[k][tx*8]);
      float4 b1 = *reinterpret_cast<const float4*>(&Bc[k][tx*8+4]);
      b[0]=b0.x; b[1]=b0.y; b[2]=b0.z; b[3]=b0.w;
      b[4]=b1.x; b[5]=b1.y; b[6]=b1.z; b[7]=b1.w;
      #pragma unroll
      for (int u=0;u<TM;u++)
        #pragma unroll
        for (int v=0;v<8;v++) acc[u][v] += a[u]*b[v];
    }
    if (kt+1 < KT){
      #pragma unroll
      for (int it=0; it<NA; it++){
        int e = tid + it*256;
        As[nxt][e&15][e>>4] = ra[it];
      }
      #pragma unroll
      for (int it=0; it<2; it++){
        int e4 = tid + it*256;
        *reinterpret_cast<float4*>(&Bs[nxt][e4/32][(e4%32)*4]) = rb[it];
      }
    }
    __syncthreads();
  }
  const float* R = RES ? (Rb + (long)blockIdx.z * sC) : (const float*)0;
  #pragma unroll
  for (int u=0;u<TM;u++){
    int m = m0+ty*TM+u;
    long off = (long)m*N + n0 + tx*8;
    float4 o0 = make_float4(acc[u][0],acc[u][1],acc[u][2],acc[u][3]);
    float4 o1 = make_float4(acc[u][4],acc[u][5],acc[u][6],acc[u][7]);
    if (RES){
      float4 r0 = *reinterpret_cast<const float4*>(&R[off]);
      float4 r1 = *reinterpret_cast<const float4*>(&R[off+4]);
      o0.x+=r0.x; o0.y+=r0.y; o0.z+=r0.z; o0.w+=r0.w;
      o1.x+=r1.x; o1.y+=r1.y; o1.z+=r1.z; o1.w+=r1.w;
    }
    *reinterpret_cast<float4*>(&C[off])   = o0;
    *reinterpret_cast<float4*>(&C[off+4]) = o1;
  }
  if (STAT){
    #pragma unroll
    for (int u=0;u<TM;u++){
      int m = m0+ty*TM+u;
      float rs=0.f, rq=0.f;
      #pragma unroll
      for (int v=0;v<8;v++){ float t=acc[u][v]; rs+=t; rq+=t*t; }
      #pragma unroll
      for (int off=8; off; off>>=1){
        rs += __shfl_xor_sync(0xffffffffu, rs, off);
        rq += __shfl_xor_sync(0xffffffffu, rq, off);
      }
      if (tx==0){
        atomicAdd(&g_stat[m*2],   (double)rs);
        atomicAdd(&g_stat[m*2+1], (double)rq);
      }
    }
  }
}

__global__ void k_chanfin(const float* __restrict__ gamma, const float* __restrict__ beta,
                          float* __restrict__ scale, float* __restrict__ shift){
  int o = threadIdx.x; if (o>=OC) return;
  double s = g_stat[o*2], q = g_stat[o*2+1];
  double m = s/(double)BPL;
  double v = q/(double)BPL - m*m;
  double sc = (double)gamma[o]/sqrt(v + 1e-5);
  scale[o] = (float)sc;
  shift[o] = (float)((double)beta[o] - m*sc);
  g_stat[o*2]=0.0; g_stat[o*2+1]=0.0;
}

__global__ void k_tables(const float* __restrict__ rel){
  int b = blockIdx.x, i = threadIdx.x;
  if (b < 12){
    float s=0.f;
    for (int d=0;d<96;d++) s += rel[b*191 + i + d];
    g_se[b*96+i] = s;
  } else if (b < 33){
    int p = b-12; int a=PA[p], bb=PB[p];
    float s=0.f;
    for (int d=0;d<96;d++) s += rel[a*191+i+d]*rel[bb*191+i+d];
    g_Pq[p*96+i]=s;
  } else {
    int p = b-33; int a=PA[p], bb=PB[p];
    float s=0.f;
    for (int d=0;d<96;d++) s += rel[(6+a)*191+i+d]*rel[(6+bb)*191+i+d];
    g_Pk[p*96+i]=s;
  }
}

__global__ void k_pass1(){
  int bp = blockIdx.x, g = blockIdx.y, i = threadIdx.x;
  int base = g*24;
  long col = (long)bp*96 + i;
  float q[6], k[6];
  #pragma unroll
  for (int c=0;c<6;c++){
    int oq = base+c;   q[c] = g_qkv2[(long)oq*BPL+col]*g_scale[oq]+g_shift[oq];
    int ok = base+6+c; k[c] = g_qkv2[(long)ok*BPL+col]*g_scale[ok]+g_shift[ok];
  }
  float qr_s=0.f, kr_s=0.f, qr_ss=0.f, kr_ss=0.f;
  #pragma unroll
  for (int c=0;c<6;c++){ qr_s += q[c]*g_se[c*96+i]; kr_s += k[c]*g_se[(6+c)*96+i]; }
  #pragma unroll
  for (int p=0;p<21;p++){
    int a=PA[p], b=PB[p];
    float f = (a==b)?1.f:2.f;
    qr_ss += f*q[a]*q[b]*g_Pq[p*96+i];
    kr_ss += f*k[a]*k[b]*g_Pk[p*96+i];
  }
  __shared__ float qs[6][96], ks2[6][96], rbuf[4][96], agg[58];
  #pragma unroll
  for (int c=0;c<6;c++){ qs[c][i]=q[c]; ks2[c][i]=k[c]; }
  rbuf[0][i]=qr_s; rbuf[1][i]=qr_ss; rbuf[2][i]=kr_s; rbuf[3][i]=kr_ss;
  __syncthreads();
  if (i < 58){
    float s=0.f;
    if (i<6)       { for (int t=0;t<96;t++) s += qs[i][t]; }
    else if (i<12) { for (int t=0;t<96;t++) s += ks2[i-6][t]; }
    else if (i<33) { int a=PA[i-12], b=PB[i-12]; for (int t=0;t<96;t++) s += qs[a][t]*qs[b][t]; }
    else if (i<54) { int a=PA[i-33], b=PB[i-33]; for (int t=0;t<96;t++) s += ks2[a][t]*ks2[b][t]; }
    else           { int r=i-54; for (int t=0;t<96;t++) s += rbuf[r][t]; }
    agg[i]=s;
  }
  __syncthreads();
  if (i==0){
    double sum_qk=0.0, ss_qk=0.0;
    for (int c=0;c<6;c++) sum_qk += (double)agg[c]*(double)agg[6+c];
    for (int p=0;p<21;p++){
      double f = (PA[p]==PB[p])?1.0:2.0;
      ss_qk += f*(double)agg[12+p]*(double)agg[33+p];
    }
    double* pp = g_part + ((long)bp*8+g)*6;
    pp[0]=sum_qk; pp[1]=ss_qk;
    pp[2]=(double)agg[54]; pp[3]=(double)agg[55];
    pp[4]=(double)agg[56]; pp[5]=(double)agg[57];
  }
}

__global__ void k_simfinal(const float* __restrict__ gs, const float* __restrict__ bs){
  int t = threadIdx.x; if (t>=24) return;
  int g = t%8, kind = t/8;
  double s=0.0, q=0.0;
  for (int bp=0; bp<384; bp++){
    const double* p = g_part + ((long)bp*8+g)*6 + kind*2;
    s += p[0]; q += p[1];
  }
  double cnt = 3538944.0;
  double m = s/cnt, v = q/cnt - m*m;
  double sc = (double)gs[t]/sqrt(v + 1e-5);
  g_sscale[t] = (float)sc;
  g_sshift[t] = (float)((double)bs[t] - m*sc);
}

// fused attention: 2 batch-lines per block (shared rel tables), no-max softmax
__global__ void __launch_bounds__(96,4) k_pass2(const float* __restrict__ rel){
  __shared__ __align__(16) float rel_s[4584];
  __shared__ __align__(16) float ks[2][96][8];
  __shared__ __align__(16) float vs[2][96][12];
  int bp0 = blockIdx.x*2, g = blockIdx.y, i = threadIdx.x;
  int base = g*24;
  {
    const float4* r4 = reinterpret_cast<const float4*>(rel);
    float4* s4 = reinterpret_cast<float4*>(rel_s);
    #pragma unroll
    for (int t=0;t<12;t++){
      int idx = i + t*96;
      if (idx < 1146) s4[idx] = r4[idx];
    }
  }
  #pragma unroll
  for (int b=0;b<2;b++){
    long col = (long)(bp0+b)*96 + i;
    #pragma unroll
    for (int c=0;c<6;c++){
      int o = base+6+c;
      ks[b][i][c] = g_qkv2[(long)o*BPL+col]*g_scale[o]+g_shift[o];
    }
    #pragma unroll
    for (int c=0;c<12;c++){
      int o = base+12+c;
      vs[b][i][c] = g_qkv2[(long)o*BPL+col]*g_scale[o]+g_shift[o];
    }
  }
  float q[2][6];
  #pragma unroll
  for (int b=0;b<2;b++)
    #pragma unroll
    for (int c=0;c<6;c++){
      int o = base+c;
      q[b][c] = g_qkv2[(long)o*BPL+(long)(bp0+b)*96+i]*g_scale[o]+g_shift[o];
    }
  float aqk=g_sscale[g], aqr=g_sscale[8+g], akr=g_sscale[16+g];
  float bsum=g_sshift[g]+g_sshift[8+g]+g_sshift[16+g];
  __syncthreads();
  float l[2] = {0.f, 0.f};
  float sv[2][12], sve[2][12];
  #pragma unroll
  for (int b=0;b<2;b++)
    #pragma unroll
    for (int c=0;c<12;c++){ sv[b][c]=0.f; sve[b][c]=0.f; }
  for (int j=0;j<96;j++){
    int dq = i - j + 95, dk = j - i + 95;
    float rq[6], rk[6], rv[12];
    #pragma unroll
    for (int c=0;c<6;c++){
      rq[c] = rel_s[c*191+dq];
      rk[c] = rel_s[(6+c)*191+dk];
    }
    #pragma unroll
    for (int c=0;c<12;c++) rv[c] = rel_s[(12+c)*191+dq];
    #pragma unroll
    for (int b=0;b<2;b++){
      float kk=0.f, qr=0.f, kr=0.f;
      #pragma unroll
      for (int c=0;c<6;c++){
        float kc = ks[b][j][c];
        kk += q[b][c]*kc;
        qr += q[b][c]*rq[c];
        kr += kc*rk[c];
      }
      float e = __expf(aqk*kk + aqr*qr + akr*kr + bsum);
      l[b] += e;
      const float4* v4 = reinterpret_cast<const float4*>(vs[b][j]);
      float4 va = v4[0], vb = v4[1], vc = v4[2];
      sv[b][0]+=e*va.x; sv[b][1]+=e*va.y; sv[b][2]+=e*va.z; sv[b][3]+=e*va.w;
      sv[b][4]+=e*vb.x; sv[b][5]+=e*vb.y; sv[b][6]+=e*vb.z; sv[b][7]+=e*vb.w;
      sv[b][8]+=e*vc.x; sv[b][9]+=e*vc.y; sv[b][10]+=e*vc.z; sv[b][11]+=e*vc.w;
      #pragma unroll
      for (int c=0;c<12;c++) sve[b][c] += e*rv[c];
    }
  }
  float rl[2] = {1.f/l[0], 1.f/l[1]};
  #pragma unroll
  for (int c=0;c<12;c++){
    float v00 = sv[0][c]*rl[0], v01 = sve[0][c]*rl[0];
    float v10 = sv[1][c]*rl[1], v11 = sve[1][c]*rl[1];
    g_ao2[(long)(base+2*c)*BPL   + (long)bp0*96 + i]     = v00;
    g_ao2[(long)(base+2*c+1)*BPL + (long)bp0*96 + i]     = v01;
    g_ao2[(long)(base+2*c)*BPL   + (long)(bp0+1)*96 + i] = v10;
    g_ao2[(long)(base+2*c+1)*BPL + (long)(bp0+1)*96 + i] = v11;
    float s0=v00+v10, q0=v00*v00+v10*v10;
    float s1=v01+v11, q1=v01*v01+v11*v11;
    #pragma unroll
    for (int off=16; off; off>>=1){
      s0 += __shfl_xor_sync(0xffffffffu, s0, off);
      q0 += __shfl_xor_sync(0xffffffffu, q0, off);
      s1 += __shfl_xor_sync(0xffffffffu, s1, off);
      q1 += __shfl_xor_sync(0xffffffffu, q1, off);
    }
    if ((i & 31)==0){
      atomicAdd(&g_stat[(base+2*c)*2],     (double)s0);
      atomicAdd(&g_stat[(base+2*c)*2+1],   (double)q0);
      atomicAdd(&g_stat[(base+2*c+1)*2],   (double)s1);
      atomicAdd(&g_stat[(base+2*c+1)*2+1], (double)q1);
    }
  }
}

// unpack height result directly into g_yt2 (width-direction layout)
__global__ void k_unpackH(){
  __shared__ float t[32][33];
  int nc = blockIdx.z; int n = nc/CD, c = nc%CD;
  int o0 = (c/12)*24 + (c%12)*2;
  float s0=g_oscale[o0], f0=g_oshift[o0], s1=g_oscale[o0+1], f1=g_oshift[o0+1];
  int hh0 = blockIdx.y*32, ww0 = blockIdx.x*32;
  long cb = (long)n*PLANE;
  int w = ww0+threadIdx.y, h = hh0+threadIdx.x;
  float a0 = g_ao2[(long)o0*BPL     + cb + w*LL + h];
  float a1 = g_ao2[(long)(o0+1)*BPL + cb + w*LL + h];
  t[threadIdx.y][threadIdx.x] = s0*a0+f0 + s1*a1+f1;
  __syncthreads();
  g_yt2[(long)c*BPL + (long)n*PLANE + (hh0+threadIdx.y)*LL + ww0+threadIdx.x] = t[threadIdx.x][threadIdx.y];
}

// fused: width unpack + residual + LN2 (per-pixel)
__global__ void k_resln(const float* __restrict__ x, const float* __restrict__ w,
                        const float* __restrict__ b){
  __shared__ float sc0[CD], sc1[CD], ff[CD], lw[CD], lb[CD];
  int tloc = threadIdx.x;
  if (tloc < CD){
    int c = tloc;
    int o0 = (c/12)*24 + (c%12)*2;
    sc0[c]=g_oscale[o0]; sc1[c]=g_oscale[o0+1];
    ff[c]=g_oshift[o0]+g_oshift[o0+1];
    lw[c]=w[c]; lb[c]=b[c];
  }
  __syncthreads();
  int pix = blockIdx.x*blockDim.x + threadIdx.x;
  if (pix >= NPIX) return;
  int n = pix / PLANE, hw = pix % PLANE;
  long col = (long)n*PLANE + hw;
  const float* xp = x + (long)n*CD*PLANE + hw;
  float* rp = g_res + (long)n*CD*PLANE + hw;
  float s=0.f, ss=0.f;
  #pragma unroll 4
  for (int c=0;c<CD;c++){
    int o0 = (c/12)*24 + (c%12)*2;
    float v = xp[(long)c*PLANE]
            + sc0[c]*g_ao2[(long)o0*BPL+col]
            + sc1[c]*g_ao2[(long)(o0+1)*BPL+col] + ff[c];
    rp[(long)c*PLANE] = v;
    s += v; ss += v*v;
  }
  float mn = s*(1.f/CD);
  float inv = rsqrtf(ss*(1.f/CD) - mn*mn + EPSF);
  float* op = g_ln + (long)n*CD*PLANE + hw;
  #pragma unroll 4
  for (int c=0;c<CD;c++){
    float v = rp[(long)c*PLANE];
    op[(long)c*PLANE] = (v-mn)*inv*lw[c] + lb[c];
  }
}

__global__ void k_dwgelu(const float* __restrict__ wdw){
  int idx = blockIdx.x*blockDim.x + threadIdx.x;
  const int W4 = LL/4, P4 = PLANE/4;
  if (idx >= NB*HID*P4) return;
  int n = idx / (HID*P4);
  int rem = idx % (HID*P4);
  int c = rem / P4;
  int hw4 = rem % P4;
  int h = hw4 / W4, w = (hw4 % W4)*4;
  const float* h1 = g_h + ((long)n*HP + c)*PLANE;
  const float* h2 = h1 + (long)HID*PLANE;
  const float* w1 = wdw + c*9;
  const float* w2 = w1 + HID*9;
  float a1[4]={0.f,0.f,0.f,0.f}, a2[4]={0.f,0.f,0.f,0.f};
  #pragma unroll
  for (int ky=0;ky<3;ky++){
    int hh = h+ky-1;
    if (hh<0 || hh>=LL) continue;
    const float* r1 = h1 + hh*LL;
    const float* r2 = h2 + hh*LL;
    float l1[6], l2[6];
    float4 m1 = *reinterpret_cast<const float4*>(&r1[w]);
    float4 m2 = *reinterpret_cast<const float4*>(&r2[w]);
    l1[1]=m1.x; l1[2]=m1.y; l1[3]=m1.z; l1[4]=m1.w;
    l2[1]=m2.x; l2[2]=m2.y; l2[3]=m2.z; l2[4]=m2.w;
    l1[0] = (w>0)      ? r1[w-1] : 0.f;
    l2[0] = (w>0)      ? r2[w-1] : 0.f;
    l1[5] = (w+4<LL)   ? r1[w+4] : 0.f;
    l2[5] = (w+4<LL)   ? r2[w+4] : 0.f;
    #pragma unroll
    for (int kx=0;kx<3;kx++){
      float g1=w1[ky*3+kx], g2=w2[ky*3+kx];
      #pragma unroll
      for (int j=0;j<4;j++){ a1[j]+=g1*l1[j+kx]; a2[j]+=g2*l2[j+kx]; }
    }
  }
  float4 o;
  o.x = 0.5f*a1[0]*(1.0f + erff(a1[0]*0.70710678f))*a2[0];
  o.y = 0.5f*a1[1]*(1.0f + erff(a1[1]*0.70710678f))*a2[1];
  o.z = 0.5f*a1[2]*(1.0f + erff(a1[2]*0.70710678f))*a2[2];
  o.w = 0.5f*a1[3]*(1.0f + erff(a1[3]*0.70710678f))*a2[3];
  long gidx = ((long)n*KP + c)*P4 + hw4;
  reinterpret_cast<float4*>(g_gate)[gidx] = o;
}

static void axial_dir(const float* wqkv, const float* gqkv, const float* bqkv,
                      const float* rel, const float* gsim, const float* bsim,
                      const float* gout, const float* bout,
                      float* yt2, float* qkv2,
                      float* scl, float* shf, float* oscl, float* oshf){
  k_gemm<96,6,96,1,false><<<dim3(288,2,1),256>>>(wqkv, yt2, qkv2, 0, BPL, 0, 0);
  k_chanfin<<<1,OC>>>(gqkv, bqkv, scl, shf);
  k_tables<<<54,96>>>(rel);
  k_pass1<<<dim3(384,8),96>>>();
  k_simfinal<<<1,32>>>(gsim, bsim);
  k_pass2<<<dim3(192,8),96>>>(rel);
  k_chanfin<<<1,OC>>>(gout, bout, oscl, oshf);
}

extern "C" void kernel_launch(void* const* d_in, const int* in_sizes, int n_in,
                              void* d_out, int out_size){
  const float* x      = (const float*)d_in[0];
  const float* ln1w   = (const float*)d_in[1];
  const float* ln1b   = (const float*)d_in[2];
  const float* h_wqkv = (const float*)d_in[3];
  const float* h_gqkv = (const float*)d_in[4];
  const float* h_bqkv = (const float*)d_in[5];
  const float* h_rel  = (const float*)d_in[6];
  const float* h_gsim = (const float*)d_in[7];
  const float* h_bsim = (const float*)d_in[8];
  const float* h_gout = (const float*)d_in[9];
  const float* h_bout = (const float*)d_in[10];
  const float* w_wqkv = (const float*)d_in[11];
  const float* w_gqkv = (const float*)d_in[12];
  const float* w_bqkv = (const float*)d_in[13];
  const float* w_rel  = (const float*)d_in[14];
  const float* w_gsim = (const float*)d_in[15];
  const float* w_bsim = (const float*)d_in[16];
  const float* w_gout = (const float*)d_in[17];
  const float* w_bout = (const float*)d_in[18];
  const float* ln2w   = (const float*)d_in[19];
  const float* ln2b   = (const float*)d_in[20];
  const float* win    = (const float*)d_in[21];
  const float* wdw    = (const float*)d_in[22];
  const float* wout   = (const float*)d_in[23];
  float* out = (float*)d_out;

  float *yt2, *qkv2, *scl, *shf, *oscl, *oshf, *resb, *lnb, *hb, *gateb, *winp, *woutp;
  cudaGetSymbolAddress((void**)&yt2,  g_yt2);
  cudaGetSymbolAddress((void**)&qkv2, g_qkv2);
  cudaGetSymbolAddress((void**)&scl,  g_scale);
  cudaGetSymbolAddress((void**)&shf,  g_shift);
  cudaGetSymbolAddress((void**)&oscl, g_oscale);
  cudaGetSymbolAddress((void**)&oshf, g_oshift);
  cudaGetSymbolAddress((void**)&resb, g_res);
  cudaGetSymbolAddress((void**)&lnb,  g_ln);
  cudaGetSymbolAddress((void**)&hb,   g_h);
  cudaGetSymbolAddress((void**)&gateb,g_gate);
  cudaGetSymbolAddress((void**)&winp, g_winpad);
  cudaGetSymbolAddress((void**)&woutp,g_woutpad);

  k_zerostat<<<1,256>>>();
  k_prep<<<(HP*CD+255)/256,256>>>(win, wout);
  k_ln<<<(NPIX+255)/256,256>>>(x, ln1w, ln1b);
  k_transH<<<dim3(3,3,NB*CD), dim3(32,32)>>>();
  axial_dir(h_wqkv, h_gqkv, h_bqkv, h_rel, h_gsim, h_bsim, h_gout, h_bout,
            yt2, qkv2, scl, shf, oscl, oshf);
  k_unpackH<<<dim3(3,3,NB*CD), dim3(32,32)>>>();
  axial_dir(w_wqkv, w_gqkv, w_bqkv, w_rel, w_gsim, w_bsim, w_gout, w_bout,
            yt2, qkv2, scl, shf, oscl, oshf);
  k_resln<<<(NPIX+255)/256,256>>>(x, ln2w, ln2b);
  k_gemm<128,8,96,0,false><<<dim3(72,4,NB),256>>>(winp, lnb, hb, 0, PLANE,
                                  (long)CD*PLANE, (long)HP*PLANE);
  k_dwgelu<<<((long)NB*HID*PLANE/4+255)/256,256>>>(wdw);
  k_gemm<96,6,KP,0,true><<<dim3(72,1,NB),256>>>(woutp, gateb, out, resb, PLANE,
                                  (long)KP*PLANE, (long)CD*PLANE);
}

// round 11
// speedup vs baseline: 1.1096x; 1.1096x over previous
#include <cuda_runtime.h>
#include <mma.h>
#include <math.h>

#define NB 4
#define CD 96
#define LL 96
#define PLANE 9216
#define NPIX 36864
#define BPL 36864
#define OC 192
#define HID 255
#define HP 512
#define KP 256
#define EPSF 1e-5f

__device__ float g_ln[NB*CD*PLANE];
__device__ float g_yt2[CD*BPL];
__device__ float g_qkv2[OC*BPL];
__device__ float g_ao2[OC*BPL];
__device__ float g_res[NB*CD*PLANE];
__device__ float g_h[(size_t)NB*HP*PLANE];
__device__ float g_gate[(size_t)NB*KP*PLANE];
__device__ float g_winpad[HP*CD];
__device__ float g_woutpad[CD*KP];
__device__ float g_scale[OC], g_shift[OC];
__device__ float g_oscale[OC], g_oshift[OC];
__device__ double g_part[384*8*6];
__device__ double g_stat[OC*2];
__device__ float g_sscale[24], g_sshift[24];
__device__ float g_se[12*96];
__device__ float g_Pq[21*96], g_Pk[21*96];

__device__ __constant__ int PA[21] = {0,0,0,0,0,0,1,1,1,1,1,2,2,2,2,3,3,3,4,4,5};
__device__ __constant__ int PB[21] = {0,1,2,3,4,5,1,2,3,4,5,2,3,4,5,3,4,5,4,5,5};

__global__ void k_zerostat(){
  int t = threadIdx.x;
  if (t < OC){ g_stat[t*2]=0.0; g_stat[t*2+1]=0.0; }
}

__global__ void k_prep(const float* __restrict__ win, const float* __restrict__ wout){
  int t = blockIdx.x*blockDim.x + threadIdx.x;
  if (t < HP*CD){
    int m = t/CD;
    g_winpad[t] = (m<510)? win[t] : 0.f;
  }
  if (t < CD*KP){
    int m = t/KP, k = t%KP;
    g_woutpad[t] = (k<HID)? wout[m*HID+k] : 0.f;
  }
  if (t < NB*PLANE){
    int n = t/PLANE, hw = t%PLANE;
    g_gate[((long)n*KP+HID)*PLANE + hw] = 0.f;
  }
}

__global__ void k_ln(const float* __restrict__ src, const float* __restrict__ w,
                     const float* __restrict__ b){
  int pix = blockIdx.x*blockDim.x + threadIdx.x;
  if (pix >= NPIX) return;
  int n = pix / PLANE, hw = pix % PLANE;
  const float* xp = src + (long)n*CD*PLANE + hw;
  float s=0.f, ss=0.f;
  #pragma unroll 8
  for (int c=0;c<CD;c++){ float v = xp[(long)c*PLANE]; s+=v; ss+=v*v; }
  float mn = s*(1.f/CD);
  float inv = rsqrtf(ss*(1.f/CD) - mn*mn + EPSF);
  float* op = g_ln + (long)n*CD*PLANE + hw;
  #pragma unroll 8
  for (int c=0;c<CD;c++){
    float v = xp[(long)c*PLANE];
    op[(long)c*PLANE] = (v-mn)*inv*w[c] + b[c];
  }
}

__global__ void k_transH(){
  __shared__ float t[32][33];
  int nc = blockIdx.z; int n = nc/CD, c = nc%CD;
  int h0 = blockIdx.y*32, w0 = blockIdx.x*32;
  const float* in = g_ln + (long)nc*PLANE;
  t[threadIdx.y][threadIdx.x] = in[(h0+threadIdx.y)*LL + w0+threadIdx.x];
  __syncthreads();
  g_yt2[(long)c*BPL + n*PLANE + (w0+threadIdx.y)*LL + (h0+threadIdx.x)] = t[threadIdx.x][threadIdx.y];
}

// tf32 tensor-core GEMM. 256 threads = 8 warps (2 m x 4 n).
// Block tile: (32*WM) x 128. Warp tile: (16*WM) x 32. No smem, no syncs.
template<int WM,int KTOT,bool RES>
__global__ void __launch_bounds__(256) k_wgemm(const float* __restrict__ A,
                        const float* __restrict__ Bb,
                        float* __restrict__ Cb, const float* __restrict__ Rb,
                        int N, long sB, long sC){
  using namespace nvcuda;
  const float* B = Bb + (long)blockIdx.z * sB;
  float* C = Cb + (long)blockIdx.z * sC;
  int warpId = threadIdx.x >> 5;
  int wm = warpId >> 2, wn = warpId & 3;
  int m0 = blockIdx.y*(32*WM) + wm*(16*WM);
  int n0 = blockIdx.x*128 + wn*32;
  wmma::fragment<wmma::accumulator,16,16,8,float> acc[WM][2];
  #pragma unroll
  for (int f=0;f<WM;f++)
    #pragma unroll
    for (int g=0;g<2;g++) wmma::fill_fragment(acc[f][g], 0.f);
  for (int k=0;k<KTOT;k+=8){
    wmma::fragment<wmma::matrix_a,16,16,8,wmma::precision::tf32,wmma::row_major> a[WM];
    wmma::fragment<wmma::matrix_b,16,16,8,wmma::precision::tf32,wmma::row_major> b[2];
    #pragma unroll
    for (int f=0;f<WM;f++){
      wmma::load_matrix_sync(a[f], A + (long)(m0+f*16)*KTOT + k, KTOT);
      #pragma unroll
      for (int i=0;i<a[f].num_elements;i++) a[f].x[i] = wmma::__float_to_tf32(a[f].x[i]);
    }
    #pragma unroll
    for (int g=0;g<2;g++){
      wmma::load_matrix_sync(b[g], B + (long)k*N + n0 + g*16, N);
      #pragma unroll
      for (int i=0;i<b[g].num_elements;i++) b[g].x[i] = wmma::__float_to_tf32(b[g].x[i]);
    }
    #pragma unroll
    for (int f=0;f<WM;f++)
      #pragma unroll
      for (int g=0;g<2;g++) wmma::mma_sync(acc[f][g], a[f], b[g], acc[f][g]);
  }
  const float* R = RES ? (Rb + (long)blockIdx.z * sC) : (const float*)0;
  #pragma unroll
  for (int f=0;f<WM;f++)
    #pragma unroll
    for (int g=0;g<2;g++){
      long off = (long)(m0+f*16)*N + n0 + g*16;
      if (RES){
        wmma::fragment<wmma::accumulator,16,16,8,float> cr;
        wmma::load_matrix_sync(cr, R + off, N, wmma::mem_row_major);
        #pragma unroll
        for (int i=0;i<cr.num_elements;i++) acc[f][g].x[i] += cr.x[i];
      }
      wmma::store_matrix_sync(C + off, acc[f][g], N, wmma::mem_row_major);
    }
}

// per-channel stats: fp32 inner accumulation, fp64 tree + atomic
__global__ void k_stats32(const float* __restrict__ X){
  int o = blockIdx.x, sl = blockIdx.y;
  const float4* p = reinterpret_cast<const float4*>(X + (long)o*BPL) + sl*1536;
  float s=0.f, ss=0.f;
  #pragma unroll
  for (int it=0; it<6; it++){
    float4 v = p[threadIdx.x + it*256];
    s  += v.x+v.y+v.z+v.w;
    ss += v.x*v.x+v.y*v.y+v.z*v.z+v.w*v.w;
  }
  __shared__ double rs[256], rq[256];
  rs[threadIdx.x]=(double)s; rq[threadIdx.x]=(double)ss; __syncthreads();
  for (int st=128; st>0; st>>=1){
    if (threadIdx.x<st){ rs[threadIdx.x]+=rs[threadIdx.x+st]; rq[threadIdx.x]+=rq[threadIdx.x+st]; }
    __syncthreads();
  }
  if (threadIdx.x==0){
    atomicAdd(&g_stat[o*2],   rs[0]);
    atomicAdd(&g_stat[o*2+1], rq[0]);
  }
}

__global__ void k_chanfin(const float* __restrict__ gamma, const float* __restrict__ beta,
                          float* __restrict__ scale, float* __restrict__ shift){
  int o = threadIdx.x; if (o>=OC) return;
  double s = g_stat[o*2], q = g_stat[o*2+1];
  double m = s/(double)BPL;
  double v = q/(double)BPL - m*m;
  double sc = (double)gamma[o]/sqrt(v + 1e-5);
  scale[o] = (float)sc;
  shift[o] = (float)((double)beta[o] - m*sc);
  g_stat[o*2]=0.0; g_stat[o*2+1]=0.0;
}

__global__ void k_tables(const float* __restrict__ rel){
  int b = blockIdx.x, i = threadIdx.x;
  if (b < 12){
    float s=0.f;
    for (int d=0;d<96;d++) s += rel[b*191 + i + d];
    g_se[b*96+i] = s;
  } else if (b < 33){
    int p = b-12; int a=PA[p], bb=PB[p];
    float s=0.f;
    for (int d=0;d<96;d++) s += rel[a*191+i+d]*rel[bb*191+i+d];
    g_Pq[p*96+i]=s;
  } else {
    int p = b-33; int a=PA[p], bb=PB[p];
    float s=0.f;
    for (int d=0;d<96;d++) s += rel[(6+a)*191+i+d]*rel[(6+bb)*191+i+d];
    g_Pk[p*96+i]=s;
  }
}

__global__ void k_pass1(){
  int bp = blockIdx.x, g = blockIdx.y, i = threadIdx.x;
  int base = g*24;
  long col = (long)bp*96 + i;
  float q[6], k[6];
  #pragma unroll
  for (int c=0;c<6;c++){
    int oq = base+c;   q[c] = g_qkv2[(long)oq*BPL+col]*g_scale[oq]+g_shift[oq];
    int ok = base+6+c; k[c] = g_qkv2[(long)ok*BPL+col]*g_scale[ok]+g_shift[ok];
  }
  float qr_s=0.f, kr_s=0.f, qr_ss=0.f, kr_ss=0.f;
  #pragma unroll
  for (int c=0;c<6;c++){ qr_s += q[c]*g_se[c*96+i]; kr_s += k[c]*g_se[(6+c)*96+i]; }
  #pragma unroll
  for (int p=0;p<21;p++){
    int a=PA[p], b=PB[p];
    float f = (a==b)?1.f:2.f;
    qr_ss += f*q[a]*q[b]*g_Pq[p*96+i];
    kr_ss += f*k[a]*k[b]*g_Pk[p*96+i];
  }
  __shared__ float qs[6][96], ks2[6][96], rbuf[4][96], agg[58];
  #pragma unroll
  for (int c=0;c<6;c++){ qs[c][i]=q[c]; ks2[c][i]=k[c]; }
  rbuf[0][i]=qr_s; rbuf[1][i]=qr_ss; rbuf[2][i]=kr_s; rbuf[3][i]=kr_ss;
  __syncthreads();
  if (i < 58){
    float s=0.f;
    if (i<6)       { for (int t=0;t<96;t++) s += qs[i][t]; }
    else if (i<12) { for (int t=0;t<96;t++) s += ks2[i-6][t]; }
    else if (i<33) { int a=PA[i-12], b=PB[i-12]; for (int t=0;t<96;t++) s += qs[a][t]*qs[b][t]; }
    else if (i<54) { int a=PA[i-33], b=PB[i-33]; for (int t=0;t<96;t++) s += ks2[a][t]*ks2[b][t]; }
    else           { int r=i-54; for (int t=0;t<96;t++) s += rbuf[r][t]; }
    agg[i]=s;
  }
  __syncthreads();
  if (i==0){
    double sum_qk=0.0, ss_qk=0.0;
    for (int c=0;c<6;c++) sum_qk += (double)agg[c]*(double)agg[6+c];
    for (int p=0;p<21;p++){
      double f = (PA[p]==PB[p])?1.0:2.0;
      ss_qk += f*(double)agg[12+p]*(double)agg[33+p];
    }
    double* pp = g_part + ((long)bp*8+g)*6;
    pp[0]=sum_qk; pp[1]=ss_qk;
    pp[2]=(double)agg[54]; pp[3]=(double)agg[55];
    pp[4]=(double)agg[56]; pp[5]=(double)agg[57];
  }
}

__global__ void k_simfinal(const float* __restrict__ gs, const float* __restrict__ bs){
  int t = threadIdx.x; if (t>=24) return;
  int g = t%8, kind = t/8;
  double s=0.0, q=0.0;
  for (int bp=0; bp<384; bp++){
    const double* p = g_part + ((long)bp*8+g)*6 + kind*2;
    s += p[0]; q += p[1];
  }
  double cnt = 3538944.0;
  double m = s/cnt, v = q/cnt - m*m;
  double sc = (double)gs[t]/sqrt(v + 1e-5);
  g_sscale[t] = (float)sc;
  g_sshift[t] = (float)((double)bs[t] - m*sc);
}

// fused attention: 2 batch-lines per block (shared rel tables), no-max softmax
__global__ void __launch_bounds__(96,4) k_pass2(const float* __restrict__ rel){
  __shared__ __align__(16) float rel_s[4584];
  __shared__ __align__(16) float ks[2][96][8];
  __shared__ __align__(16) float vs[2][96][12];
  int bp0 = blockIdx.x*2, g = blockIdx.y, i = threadIdx.x;
  int base = g*24;
  {
    const float4* r4 = reinterpret_cast<const float4*>(rel);
    float4* s4 = reinterpret_cast<float4*>(rel_s);
    #pragma unroll
    for (int t=0;t<12;t++){
      int idx = i + t*96;
      if (idx < 1146) s4[idx] = r4[idx];
    }
  }
  #pragma unroll
  for (int b=0;b<2;b++){
    long col = (long)(bp0+b)*96 + i;
    #pragma unroll
    for (int c=0;c<6;c++){
      int o = base+6+c;
      ks[b][i][c] = g_qkv2[(long)o*BPL+col]*g_scale[o]+g_shift[o];
    }
    #pragma unroll
    for (int c=0;c<12;c++){
      int o = base+12+c;
      vs[b][i][c] = g_qkv2[(long)o*BPL+col]*g_scale[o]+g_shift[o];
    }
  }
  float q[2][6];
  #pragma unroll
  for (int b=0;b<2;b++)
    #pragma unroll
    for (int c=0;c<6;c++){
      int o = base+c;
      q[b][c] = g_qkv2[(long)o*BPL+(long)(bp0+b)*96+i]*g_scale[o]+g_shift[o];
    }
  float aqk=g_sscale[g], aqr=g_sscale[8+g], akr=g_sscale[16+g];
  float bsum=g_sshift[g]+g_sshift[8+g]+g_sshift[16+g];
  __syncthreads();
  float l[2] = {0.f, 0.f};
  float sv[2][12], sve[2][12];
  #pragma unroll
  for (int b=0;b<2;b++)
    #pragma unroll
    for (int c=0;c<12;c++){ sv[b][c]=0.f; sve[b][c]=0.f; }
  for (int j=0;j<96;j++){
    int dq = i - j + 95, dk = j - i + 95;
    float rq[6], rk[6], rv[12];
    #pragma unroll
    for (int c=0;c<6;c++){
      rq[c] = rel_s[c*191+dq];
      rk[c] = rel_s[(6+c)*191+dk];
    }
    #pragma unroll
    for (int c=0;c<12;c++) rv[c] = rel_s[(12+c)*191+dq];
    #pragma unroll
    for (int b=0;b<2;b++){
      float kk=0.f, qr=0.f, kr=0.f;
      #pragma unroll
      for (int c=0;c<6;c++){
        float kc = ks[b][j][c];
        kk += q[b][c]*kc;
        qr += q[b][c]*rq[c];
        kr += kc*rk[c];
      }
      float e = __expf(aqk*kk + aqr*qr + akr*kr + bsum);
      l[b] += e;
      const float4* v4 = reinterpret_cast<const float4*>(vs[b][j]);
      float4 va = v4[0], vb = v4[1], vc = v4[2];
      sv[b][0]+=e*va.x; sv[b][1]+=e*va.y; sv[b][2]+=e*va.z; sv[b][3]+=e*va.w;
      sv[b][4]+=e*vb.x; sv[b][5]+=e*vb.y; sv[b][6]+=e*vb.z; sv[b][7]+=e*vb.w;
      sv[b][8]+=e*vc.x; sv[b][9]+=e*vc.y; sv[b][10]+=e*vc.z; sv[b][11]+=e*vc.w;
      #pragma unroll
      for (int c=0;c<12;c++) sve[b][c] += e*rv[c];
    }
  }
  float rl[2] = {1.f/l[0], 1.f/l[1]};
  #pragma unroll
  for (int c=0;c<12;c++){
    float v00 = sv[0][c]*rl[0], v01 = sve[0][c]*rl[0];
    float v10 = sv[1][c]*rl[1], v11 = sve[1][c]*rl[1];
    g_ao2[(long)(base+2*c)*BPL   + (long)bp0*96 + i]     = v00;
    g_ao2[(long)(base+2*c+1)*BPL + (long)bp0*96 + i]     = v01;
    g_ao2[(long)(base+2*c)*BPL   + (long)(bp0+1)*96 + i] = v10;
    g_ao2[(long)(base+2*c+1)*BPL + (long)(bp0+1)*96 + i] = v11;
    float s0=v00+v10, q0=v00*v00+v10*v10;
    float s1=v01+v11, q1=v01*v01+v11*v11;
    #pragma unroll
    for (int off=16; off; off>>=1){
      s0 += __shfl_xor_sync(0xffffffffu, s0, off);
      q0 += __shfl_xor_sync(0xffffffffu, q0, off);
      s1 += __shfl_xor_sync(0xffffffffu, s1, off);
      q1 += __shfl_xor_sync(0xffffffffu, q1, off);
    }
    if ((i & 31)==0){
      atomicAdd(&g_stat[(base+2*c)*2],     (double)s0);
      atomicAdd(&g_stat[(base+2*c)*2+1],   (double)q0);
      atomicAdd(&g_stat[(base+2*c+1)*2],   (double)s1);
      atomicAdd(&g_stat[(base+2*c+1)*2+1], (double)q1);
    }
  }
}

// unpack height result directly into g_yt2 (width-direction layout)
__global__ void k_unpackH(){
  __shared__ float t[32][33];
  int nc = blockIdx.z; int n = nc/CD, c = nc%CD;
  int o0 = (c/12)*24 + (c%12)*2;
  float s0=g_oscale[o0], f0=g_oshift[o0], s1=g_oscale[o0+1], f1=g_oshift[o0+1];
  int hh0 = blockIdx.y*32, ww0 = blockIdx.x*32;
  long cb = (long)n*PLANE;
  int w = ww0+threadIdx.y, h = hh0+threadIdx.x;
  float a0 = g_ao2[(long)o0*BPL     + cb + w*LL + h];
  float a1 = g_ao2[(long)(o0+1)*BPL + cb + w*LL + h];
  t[threadIdx.y][threadIdx.x] = s0*a0+f0 + s1*a1+f1;
  __syncthreads();
  g_yt2[(long)c*BPL + (long)n*PLANE + (hh0+threadIdx.y)*LL + ww0+threadIdx.x] = t[threadIdx.x][threadIdx.y];
}

__global__ void k_unpackW(const float* __restrict__ x){
  int idx = blockIdx.x*blockDim.x + threadIdx.x;
  const int P4 = PLANE/4;
  if (idx >= NB*CD*P4) return;
  int n = idx / (CD*P4);
  int rem = idx % (CD*P4);
  int c = rem / P4;
  int hw4 = rem % P4;
  int o0 = (c/12)*24 + (c%12)*2;
  long col4 = (long)n*P4 + hw4;
  float4 a0 = reinterpret_cast<const float4*>(g_ao2)[(long)o0*(BPL/4)+col4];
  float4 a1 = reinterpret_cast<const float4*>(g_ao2)[(long)(o0+1)*(BPL/4)+col4];
  float4 xv = reinterpret_cast<const float4*>(x)[(long)idx];
  float s0=g_oscale[o0], f0=g_oshift[o0], s1=g_oscale[o0+1], f1=g_oshift[o0+1];
  float4 r;
  r.x = xv.x + s0*a0.x+f0 + s1*a1.x+f1;
  r.y = xv.y + s0*a0.y+f0 + s1*a1.y+f1;
  r.z = xv.z + s0*a0.z+f0 + s1*a1.z+f1;
  r.w = xv.w + s0*a0.w+f0 + s1*a1.w+f1;
  reinterpret_cast<float4*>(g_res)[(long)idx] = r;
}

__global__ void k_dwgelu(const float* __restrict__ wdw){
  int idx = blockIdx.x*blockDim.x + threadIdx.x;
  const int W4 = LL/4, P4 = PLANE/4;
  if (idx >= NB*HID*P4) return;
  int n = idx / (HID*P4);
  int rem = idx % (HID*P4);
  int c = rem / P4;
  int hw4 = rem % P4;
  int h = hw4 / W4, w = (hw4 % W4)*4;
  const float* h1 = g_h + ((long)n*HP + c)*PLANE;
  const float* h2 = h1 + (long)HID*PLANE;
  const float* w1 = wdw + c*9;
  const float* w2 = w1 + HID*9;
  float a1[4]={0.f,0.f,0.f,0.f}, a2[4]={0.f,0.f,0.f,0.f};
  #pragma unroll
  for (int ky=0;ky<3;ky++){
    int hh = h+ky-1;
    if (hh<0 || hh>=LL) continue;
    const float* r1 = h1 + hh*LL;
    const float* r2 = h2 + hh*LL;
    float l1[6], l2[6];
    float4 m1 = *reinterpret_cast<const float4*>(&r1[w]);
    float4 m2 = *reinterpret_cast<const float4*>(&r2[w]);
    l1[1]=m1.x; l1[2]=m1.y; l1[3]=m1.z; l1[4]=m1.w;
    l2[1]=m2.x; l2[2]=m2.y; l2[3]=m2.z; l2[4]=m2.w;
    l1[0] = (w>0)      ? r1[w-1] : 0.f;
    l2[0] = (w>0)      ? r2[w-1] : 0.f;
    l1[5] = (w+4<LL)   ? r1[w+4] : 0.f;
    l2[5] = (w+4<LL)   ? r2[w+4] : 0.f;
    #pragma unroll
    for (int kx=0;kx<3;kx++){
      float g1=w1[ky*3+kx], g2=w2[ky*3+kx];
      #pragma unroll
      for (int j=0;j<4;j++){ a1[j]+=g1*l1[j+kx]; a2[j]+=g2*l2[j+kx]; }
    }
  }
  float4 o;
  o.x = 0.5f*a1[0]*(1.0f + erff(a1[0]*0.70710678f))*a2[0];
  o.y = 0.5f*a1[1]*(1.0f + erff(a1[1]*0.70710678f))*a2[1];
  o.z = 0.5f*a1[2]*(1.0f + erff(a1[2]*0.70710678f))*a2[2];
  o.w = 0.5f*a1[3]*(1.0f + erff(a1[3]*0.70710678f))*a2[3];
  long gidx = ((long)n*KP + c)*P4 + hw4;
  reinterpret_cast<float4*>(g_gate)[gidx] = o;
}

static void axial_dir(const float* wqkv, const float* gqkv, const float* bqkv,
                      const float* rel, const float* gsim, const float* bsim,
                      const float* gout, const float* bout,
                      float* yt2, float* qkv2,
                      float* scl, float* shf, float* oscl, float* oshf){
  k_wgemm<3,96,false><<<dim3(288,2,1),256>>>(wqkv, yt2, qkv2, 0, BPL, 0, 0);
  k_stats32<<<dim3(OC,6),256>>>(qkv2);
  k_chanfin<<<1,OC>>>(gqkv, bqkv, scl, shf);
  k_tables<<<54,96>>>(rel);
  k_pass1<<<dim3(384,8),96>>>();
  k_simfinal<<<1,32>>>(gsim, bsim);
  k_pass2<<<dim3(192,8),96>>>(rel);
  k_chanfin<<<1,OC>>>(gout, bout, oscl, oshf);
}

extern "C" void kernel_launch(void* const* d_in, const int* in_sizes, int n_in,
                              void* d_out, int out_size){
  const float* x      = (const float*)d_in[0];
  const float* ln1w   = (const float*)d_in[1];
  const float* ln1b   = (const float*)d_in[2];
  const float* h_wqkv = (const float*)d_in[3];
  const float* h_gqkv = (const float*)d_in[4];
  const float* h_bqkv = (const float*)d_in[5];
  const float* h_rel  = (const float*)d_in[6];
  const float* h_gsim = (const float*)d_in[7];
  const float* h_bsim = (const float*)d_in[8];
  const float* h_gout = (const float*)d_in[9];
  const float* h_bout = (const float*)d_in[10];
  const float* w_wqkv = (const float*)d_in[11];
  const float* w_gqkv = (const float*)d_in[12];
  const float* w_bqkv = (const float*)d_in[13];
  const float* w_rel  = (const float*)d_in[14];
  const float* w_gsim = (const float*)d_in[15];
  const float* w_bsim = (const float*)d_in[16];
  const float* w_gout = (const float*)d_in[17];
  const float* w_bout = (const float*)d_in[18];
  const float* ln2w   = (const float*)d_in[19];
  const float* ln2b   = (const float*)d_in[20];
  const float* win    = (const float*)d_in[21];
  const float* wdw    = (const float*)d_in[22];
  const float* wout   = (const float*)d_in[23];
  float* out = (float*)d_out;

  float *yt2, *qkv2, *scl, *shf, *oscl, *oshf, *resb, *lnb, *hb, *gateb, *winp, *woutp;
  cudaGetSymbolAddress((void**)&yt2,  g_yt2);
  cudaGetSymbolAddress((void**)&qkv2, g_qkv2);
  cudaGetSymbolAddress((void**)&scl,  g_scale);
  cudaGetSymbolAddress((void**)&shf,  g_shift);
  cudaGetSymbolAddress((void**)&oscl, g_oscale);
  cudaGetSymbolAddress((void**)&oshf, g_oshift);
  cudaGetSymbolAddress((void**)&resb, g_res);
  cudaGetSymbolAddress((void**)&lnb,  g_ln);
  cudaGetSymbolAddress((void**)&hb,   g_h);
  cudaGetSymbolAddress((void**)&gateb,g_gate);
  cudaGetSymbolAddress((void**)&winp, g_winpad);
  cudaGetSymbolAddress((void**)&woutp,g_woutpad);

  k_zerostat<<<1,256>>>();
  k_prep<<<(HP*CD+255)/256,256>>>(win, wout);
  k_ln<<<(NPIX+255)/256,256>>>(x, ln1w, ln1b);
  k_transH<<<dim3(3,3,NB*CD), dim3(32,32)>>>();
  axial_dir(h_wqkv, h_gqkv, h_bqkv, h_rel, h_gsim, h_bsim, h_gout, h_bout,
            yt2, qkv2, scl, shf, oscl, oshf);
  k_unpackH<<<dim3(3,3,NB*CD), dim3(32,32)>>>();
  axial_dir(w_wqkv, w_gqkv, w_bqkv, w_rel, w_gsim, w_bsim, w_gout, w_bout,
            yt2, qkv2, scl, shf, oscl, oshf);
  k_unpackW<<<(NB*CD*PLANE/4+255)/256,256>>>(x);
  k_ln<<<(NPIX+255)/256,256>>>(resb, ln2w, ln2b);
  k_wgemm<2,96,false><<<dim3(72,8,NB),256>>>(winp, lnb, hb, 0, PLANE,
                                  (long)CD*PLANE, (long)HP*PLANE);
  k_dwgelu<<<((long)NB*HID*PLANE/4+255)/256,256>>>(wdw);
  k_wgemm<3,256,true><<<dim3(72,1,NB),256>>>(woutp, gateb, out, resb, PLANE,
                                  (long)KP*PLANE, (long)CD*PLANE);
}